// round 12
// baseline (speedup 1.0000x reference)
#include <cuda_runtime.h>
#include <cstdint>
#include <math.h>
#include <float.h>

#define NPTS     4096
#define MAXQ     32768            // B=8 * 4096
#define SORT_THR 1024
#define NN_THR   256

typedef unsigned long long ull;

// Sorted points per (set, global row): {x, y, z, orig_idx_bits}. Rewritten
// fully on every launch -> graph-replay deterministic.
__device__ float4 g_pts[2][MAXQ];

// Order-preserving float -> uint32 (total order incl. negatives).
__device__ __forceinline__ unsigned int fkey(float f) {
    unsigned int b = __float_as_uint(f);
    return (b & 0x80000000u) ? ~b : (b | 0x80000000u);
}

// Bitonic sort of one batch of one set by z (4096 u64 keys in smem), then
// write sorted SoA float4 (x, y, z, idx_bits) to g_pts. Also zeroes out[0].
__global__ void __launch_bounds__(SORT_THR) sort_kernel(
    const float* __restrict__ X1, const float* __restrict__ X2, float* out)
{
    __shared__ ull sk[NPTS];

    const int b = blockIdx.x;                 // batch
    const int s = blockIdx.y;                 // set: 0 = X1, 1 = X2
    const int tid = threadIdx.x;
    const float* __restrict__ P = (s ? X2 : X1) + (size_t)b * NPTS * 6;

    if (b == 0 && s == 0 && tid == 0) out[0] = 0.0f;

#pragma unroll
    for (int i = tid; i < NPTS; i += SORT_THR)
        sk[i] = ((ull)fkey(P[i * 6 + 2]) << 32) | (unsigned int)i;
    __syncthreads();

    for (int k = 2; k <= NPTS; k <<= 1) {
        for (int j = k >> 1; j > 0; j >>= 1) {
#pragma unroll
            for (int t = tid; t < NPTS / 2; t += SORT_THR) {
                int i = ((t & ~(j - 1)) << 1) | (t & (j - 1));
                int p = i | j;
                bool up = ((i & k) == 0);
                ull a = sk[i], c = sk[p];
                if ((a > c) == up) { sk[i] = c; sk[p] = a; }
            }
            __syncthreads();
        }
    }

#pragma unroll
    for (int r = tid; r < NPTS; r += SORT_THR) {
        int i = (int)(unsigned int)(sk[r] & 0xFFFFFFFFull);
        const float* p = P + (size_t)i * 6;
        g_pts[s][b * NPTS + r] = make_float4(p[0], p[1], p[2],
                                             __int_as_float(i));
    }
}

__device__ __forceinline__ float normal_diff2(const float* __restrict__ a,
                                              const float* __restrict__ b) {
    float ax = a[0], ay = a[1], az = a[2];
    float bx = b[0], by = b[1], bz = b[2];
    float ia = 1.0f / fmaxf(sqrtf(fmaf(ax, ax, fmaf(ay, ay, az * az))), 1e-12f);
    float ib = 1.0f / fmaxf(sqrtf(fmaf(bx, bx, fmaf(by, by, bz * bz))), 1e-12f);
    float dx = ax * ia - bx * ib;
    float dy = ay * ia - by * ib;
    float dz = az * ia - bz * ib;
    return fmaf(dx, dx, fmaf(dy, dy, dz * dz));
}

// NN + reduce: one thread per query. Both point sets are z-sorted, so the
// query's own rank is a good starting position in the candidate list.
// Expand left/right; a side is pruned once its dz has the correct sign AND
// dz^2 >= best d (exact bound: all further candidates on that side are
// farther in z, hence farther in d). Then gather normals for the winner,
// compute dist + normal terms, block-reduce, one atomicAdd.
__global__ void __launch_bounds__(NN_THR) nn_kernel(
    const float* __restrict__ X1, const float* __restrict__ X2,
    float* __restrict__ out, float inv_nq)
{
    const int dir  = blockIdx.y;              // 0: Q=set0,C=set1  1: reverse
    const int qg   = blockIdx.x * NN_THR + threadIdx.x;   // 0..MAXQ-1
    const int batch = qg / NPTS;
    const int rank  = qg - batch * NPTS;

    const float4 q = g_pts[dir ? 1 : 0][qg];
    const float qx = q.x, qy = q.y, qz = q.z;
    const float4* __restrict__ cb = &g_pts[dir ? 0 : 1][batch * NPTS];

    float best = FLT_MAX;
    int   bidx = 0;
    int   L = rank - 1, R = rank;
    bool  goL = (L >= 0), goR = true;

    while (goL || goR) {
        if (goR) {
            float4 c = cb[R];
            float dz = c.z - qz;
            float dz2 = dz * dz;
            if (dz >= 0.0f && dz2 >= best) {
                goR = false;
            } else {
                float dx = c.x - qx, dy = c.y - qy;
                float d = fmaf(dx, dx, fmaf(dy, dy, dz2));
                if (d < best) { best = d; bidx = __float_as_int(c.w); }
                if (++R >= NPTS) goR = false;
            }
        }
        if (goL) {
            float4 c = cb[L];
            float dz = qz - c.z;
            float dz2 = dz * dz;
            if (dz >= 0.0f && dz2 >= best) {
                goL = false;
            } else {
                float dx = c.x - qx, dy = c.y - qy;
                float d = fmaf(dx, dx, fmaf(dy, dy, dz2));
                if (d < best) { best = d; bidx = __float_as_int(c.w); }
                if (--L < 0) goL = false;
            }
        }
    }

    // Normal term: query normal from its original row, neighbor normal from
    // the winning candidate's original row.
    const float* __restrict__ Qraw = dir ? X2 : X1;
    const float* __restrict__ Craw = dir ? X1 : X2;
    int qidx = __float_as_int(q.w);
    const float* nq = Qraw + (size_t)(batch * NPTS + qidx) * 6 + 3;
    const float* nc = Craw + (size_t)(batch * NPTS + bidx) * 6 + 3;
    float acc = best + normal_diff2(nq, nc);

    // Block reduction -> one atomicAdd per block.
    __shared__ float ssum[NN_THR / 32];
    float v = acc;
#pragma unroll
    for (int o = 16; o > 0; o >>= 1) v += __shfl_down_sync(0xFFFFFFFFu, v, o);
    int lane = threadIdx.x & 31, warp = threadIdx.x >> 5;
    if (lane == 0) ssum[warp] = v;
    __syncthreads();
    if (warp == 0) {
        v = (lane < NN_THR / 32) ? ssum[lane] : 0.0f;
#pragma unroll
        for (int o = 4; o > 0; o >>= 1) v += __shfl_down_sync(0xFFFFFFFFu, v, o);
        if (lane == 0) atomicAdd(out, v * inv_nq);
    }
}

extern "C" void kernel_launch(void* const* d_in, const int* in_sizes, int n_in,
                              void* d_out, int out_size)
{
    const float* x1 = (const float*)d_in[0];
    const float* x2 = (const float*)d_in[1];
    float* out = (float*)d_out;

    int total = in_sizes[0];
    int B  = total / (NPTS * 6);      // 8
    int nq = B * NPTS;                // 32768

    dim3 sgrid(B, 2);                 // (8, 2) = 16 CTAs
    sort_kernel<<<sgrid, SORT_THR>>>(x1, x2, out);

    dim3 ngrid(nq / NN_THR, 2);       // (128, 2) = 256 CTAs
    nn_kernel<<<ngrid, NN_THR>>>(x1, x2, out, 1.0f / (float)nq);
}

// round 13
// speedup vs baseline: 4.8165x; 4.8165x over previous
#include <cuda_runtime.h>
#include <cstdint>
#include <math.h>
#include <float.h>
#include <cub/cub.cuh>

#define NPTS     4096
#define MAXQ     32768            // B=8 * 4096
#define SORT_THR 1024
#define SORT_IPT 4                // 4096 / 1024
#define NN_THR   256
#define WPB      (NN_THR / 32)

typedef unsigned long long ull;

// Sorted points per (set, global row): {x, y, z, orig_idx_bits}, z ascending.
// Rewritten fully on every launch -> graph-replay deterministic.
__device__ float4 g_pts[2][MAXQ];

// Order-preserving float <-> uint32 (total order incl. negatives).
__device__ __forceinline__ unsigned int fkey(float f) {
    unsigned int b = __float_as_uint(f);
    return (b & 0x80000000u) ? ~b : (b | 0x80000000u);
}
__device__ __forceinline__ float inv_fkey(unsigned int k) {
    unsigned int b = (k & 0x80000000u) ? (k & 0x7FFFFFFFu) : ~k;
    return __uint_as_float(b);
}

// Radix-sort one (batch, set) by z. Keys = fkey(z) (exact order), values =
// original index. Writes sorted SoA float4 {x, y, z, idx} to g_pts.
__global__ void __launch_bounds__(SORT_THR) sort_kernel(
    const float* __restrict__ X1, const float* __restrict__ X2, float* out)
{
    typedef cub::BlockRadixSort<unsigned int, SORT_THR, SORT_IPT,
                                unsigned int> BRS;
    __shared__ typename BRS::TempStorage ts;

    const int b = blockIdx.x;                 // batch
    const int s = blockIdx.y;                 // set: 0 = X1, 1 = X2
    const int tid = threadIdx.x;
    const float* __restrict__ P = (s ? X2 : X1) + (size_t)b * NPTS * 6;

    if (b == 0 && s == 0 && tid == 0) out[0] = 0.0f;  // nn accumulates

    unsigned int k[SORT_IPT], v[SORT_IPT];
#pragma unroll
    for (int i = 0; i < SORT_IPT; i++) {
        int e = tid * SORT_IPT + i;
        k[i] = fkey(P[(size_t)e * 6 + 2]);
        v[i] = (unsigned int)e;
    }
    BRS(ts).Sort(k, v);                       // ascending, blocked output

#pragma unroll
    for (int i = 0; i < SORT_IPT; i++) {
        int r = tid * SORT_IPT + i;
        int idx = (int)v[i];
        float2 xy = *(const float2*)(P + (size_t)idx * 6);
        g_pts[s][b * NPTS + r] =
            make_float4(xy.x, xy.y, inv_fkey(k[i]), __int_as_float(idx));
    }
}

__device__ __forceinline__ float normal_diff2(const float* __restrict__ a,
                                              const float* __restrict__ b) {
    float ax = a[0], ay = a[1], az = a[2];
    float bx = b[0], by = b[1], bz = b[2];
    float ia = 1.0f / fmaxf(sqrtf(fmaf(ax, ax, fmaf(ay, ay, az * az))), 1e-12f);
    float ib = 1.0f / fmaxf(sqrtf(fmaf(bx, bx, fmaf(by, by, bz * bz))), 1e-12f);
    float dx = ax * ia - bx * ib;
    float dy = ay * ia - by * ib;
    float dz = az * ia - bz * ib;
    return fmaf(dx, dx, fmaf(dy, dy, dz * dz));
}

// NN + reduce: ONE WARP per query. Lanes 0-15 expand right from the query's
// own z-rank, lanes 16-31 expand left; 32 candidates per step, coalesced.
// Warp-wide best d via redux.sync.min.u32 (d >= 0 so float bits are
// uint-ordered). A side stops when its boundary lane (largest |dz| this
// step; z monotone along scan) satisfies dz > 0 && dz^2 >= best — exact
// bound: all farther candidates on that side have d >= dz^2 >= best.
// Per-lane (d, orig idx) merged at the end via packed u64 min (ties ->
// smallest original index, matching jnp.argmin).
__global__ void __launch_bounds__(NN_THR) nn_kernel(
    const float* __restrict__ X1, const float* __restrict__ X2,
    float* __restrict__ out, float inv_nq)
{
    const int dir   = blockIdx.y;             // query set = dir, cand = dir^1
    const int w     = blockIdx.x * WPB + (threadIdx.x >> 5);  // 0..MAXQ-1
    const int lane  = threadIdx.x & 31;
    const int batch = w / NPTS;
    const int rank  = w - batch * NPTS;

    const float4 q = g_pts[dir][w];
    const float4* __restrict__ cb = &g_pts[dir ^ 1][(size_t)batch * NPTS];

    const bool right = (lane < 16);
    int pos = right ? (rank + lane) : (rank - 1 - (lane - 16));

    unsigned int lbest = 0xFFFFFFFFu;          // per-lane best d bits
    int          lidx  = 0;
    unsigned int bestb = 0x7F7FFFFFu;          // FLT_MAX bits (warp best)
    bool aR = true, aL = true;

    while (aR | aL) {
        bool act = right ? aR : aL;
        bool inb = act && (pos >= 0) && (pos < NPTS);
        float4 c = inb ? cb[pos] : make_float4(0.f, 0.f, 0.f, 0.f);

        float dx = c.x - q.x, dy = c.y - q.y, dz = c.z - q.z;
        float d  = fmaf(dx, dx, fmaf(dy, dy, dz * dz));
        unsigned int db = inb ? __float_as_uint(d) : 0xFFFFFFFFu;
        if (db < lbest) { lbest = db; lidx = __float_as_int(c.w); }

        unsigned int wmin;
        asm("redux.sync.min.u32 %0, %1, 0xffffffff;" : "=r"(wmin) : "r"(db));
        bestb = min(bestb, wmin);
        float bestf = __uint_as_float(bestb);

        float dzb = right ? dz : -dz;
        bool stop = !inb || (dzb > 0.0f && dzb * dzb >= bestf);
        unsigned int bal = __ballot_sync(0xFFFFFFFFu, stop);
        if (bal & (1u << 15)) aR = false;      // right boundary lane
        if (bal & 0x80000000u) aL = false;     // left boundary lane (31)
        pos += right ? 16 : -16;
    }

    // Merge per-lane results: packed (d_bits << 32 | orig_idx); u64 min
    // gives min d, ties -> smallest original index.
    ull pk = ((ull)lbest << 32) | (unsigned int)lidx;
#pragma unroll
    for (int m = 16; m >= 1; m >>= 1) {
        ull o = __shfl_xor_sync(0xFFFFFFFFu, pk, m);
        pk = o < pk ? o : pk;
    }

    float acc = 0.0f;
    if (lane == 0) {
        float dbest = __uint_as_float((unsigned int)(pk >> 32));
        int   cidx  = (int)(pk & 0xFFFFFFFFull);
        int   qidx  = __float_as_int(q.w);
        const float* Qn = (dir ? X2 : X1)
                        + (size_t)(batch * NPTS + qidx) * 6 + 3;
        const float* Cn = (dir ? X1 : X2)
                        + (size_t)(batch * NPTS + cidx) * 6 + 3;
        acc = dbest + normal_diff2(Qn, Cn);
    }

    // Block reduction over WPB warps -> one atomicAdd per block.
    __shared__ float ssum[WPB];
    if (lane == 0) ssum[threadIdx.x >> 5] = acc;
    __syncthreads();
    if (threadIdx.x < 32) {
        float v = (lane < WPB) ? ssum[lane] : 0.0f;
#pragma unroll
        for (int o = WPB / 2; o >= 1; o >>= 1)
            v += __shfl_down_sync(0xFFFFFFFFu, v, o);
        if (lane == 0) atomicAdd(out, v * inv_nq);
    }
}

extern "C" void kernel_launch(void* const* d_in, const int* in_sizes, int n_in,
                              void* d_out, int out_size)
{
    const float* x1 = (const float*)d_in[0];
    const float* x2 = (const float*)d_in[1];
    float* out = (float*)d_out;

    int total = in_sizes[0];
    int B  = total / (NPTS * 6);      // 8
    int nq = B * NPTS;                // 32768

    dim3 sgrid(B, 2);                 // (8, 2) = 16 CTAs
    sort_kernel<<<sgrid, SORT_THR>>>(x1, x2, out);

    dim3 ngrid(nq / WPB, 2);          // (4096, 2) = 8192 CTAs, warp/query
    nn_kernel<<<ngrid, NN_THR>>>(x1, x2, out, 1.0f / (float)nq);
}